// round 9
// baseline (speedup 1.0000x reference)
#include <cuda_runtime.h>
#include <cstdint>

#define NHEADS 16
#define HID    1024
#define TT     2048
#define BB     32

typedef unsigned long long ull;

// ---------------- device scratch (no allocations allowed) ----------------
__device__ float g_wq[NHEADS * HID];
__device__ float g_c[NHEADS];
__device__ float g_logits[BB * NHEADS * TT];          // reused in-place as attn
__device__ float g_pooled[BB * NHEADS * HID];         // pooled hidden (pool writes directly)
__device__ float g_outv[BB * HID];
__device__ float g_fpart[16 * BB * HID];

#define FMA2(c, a, b) asm("fma.rn.f32x2 %0, %1, %2, %0;" : "+l"(c) : "l"(a), "l"(b))
static __device__ __forceinline__ float f2_lo(ull v) { return __uint_as_float((unsigned)(v & 0xffffffffull)); }
static __device__ __forceinline__ float f2_hi(ull v) { return __uint_as_float((unsigned)(v >> 32)); }

static __device__ __forceinline__ unsigned smaddr(const void* p) {
    return (unsigned)__cvta_generic_to_shared(p);
}
#define CP16(dst, src)  asm volatile("cp.async.cg.shared.global [%0], [%1], 16;" :: "r"(dst), "l"(src))
#define CP_COMMIT()     asm volatile("cp.async.commit_group;" ::: "memory")
#define CP_WAIT2()      asm volatile("cp.async.wait_group 2;" ::: "memory")

// tf32 helpers
static __device__ __forceinline__ unsigned cvt_tf32(float x) {
    unsigned r;
    asm("cvt.rna.tf32.f32 %0, %1;" : "=r"(r) : "f"(x));
    return r;
}
#define MMA8(d0, d1, d2, d3, a0, a1, a2, a3, b0, b1)                     \
    asm("mma.sync.aligned.m16n8k8.row.col.f32.tf32.tf32.f32 "            \
        "{%0,%1,%2,%3},{%4,%5,%6,%7},{%8,%9},{%0,%1,%2,%3};"             \
        : "+f"(d0), "+f"(d1), "+f"(d2), "+f"(d3)                         \
        : "r"(a0), "r"(a1), "r"(a2), "r"(a3), "r"(b0), "r"(b1))

// ---------------- kernel 1: fold query into kv_w (k half) ----------------
__global__ void k_wq(const float* __restrict__ q,
                     const float* __restrict__ kvw,
                     const float* __restrict__ kvb) {
    int w = blockIdx.x * (blockDim.x >> 5) + (threadIdx.x >> 5);
    int lane = threadIdx.x & 31;
    if (w < NHEADS * HID) {
        int h = w & (NHEADS - 1);
        int i = w >> 4;
        const float* wr = kvw + (size_t)i * (2 * HID) + h * 64;
        const float* qr = q + h * 64;
        float s = qr[lane] * wr[lane] + qr[lane + 32] * wr[lane + 32];
        #pragma unroll
        for (int o = 16; o; o >>= 1) s += __shfl_xor_sync(0xffffffffu, s, o);
        if (lane == 0) g_wq[h * HID + i] = 0.125f * s;
    }
    if (blockIdx.x == 0 && threadIdx.x < NHEADS) {
        int h = threadIdx.x;
        float s = 0.f;
        for (int d = 0; d < 64; d++) s += q[h * 64 + d] * kvb[h * 64 + d];
        g_c[h] = 0.125f * s;
    }
}

// ---------------- kernel 2: logits (R7-measured 3-stage version) ----------------
#define LCH 16
#define HP  20
__global__ void __launch_bounds__(128) k_logits(const float* __restrict__ hid) {
    extern __shared__ __align__(16) float hsm[];        // [3][256][20]
    __shared__ __align__(16) float wq_s[3][NHEADS][LCH];
    int tid = threadIdx.x;
    const float* hblk = hid + (size_t)blockIdx.x * 256 * HID;

    ull acc0[NHEADS], acc1[NHEADS];
    #pragma unroll
    for (int h = 0; h < NHEADS; h++) { acc0[h] = 0ull; acc1[h] = 0ull; }

    #define LFILL(st, kc)                                                          \
        do {                                                                       \
            _Pragma("unroll")                                                      \
            for (int p = 0; p < 8; p++) {                                          \
                int idx = p * 128 + tid;                                           \
                int row = idx >> 2;                                                \
                int q4  = (idx & 3) * 4;                                           \
                CP16(smaddr(hsm + ((st) * 256 + row) * HP + q4),                   \
                     hblk + (size_t)row * HID + (kc) + q4);                        \
            }                                                                      \
            if (tid < 64) {                                                        \
                int hh = tid >> 2;                                                 \
                int kq = (tid & 3) * 4;                                            \
                CP16(smaddr(&wq_s[st][hh][kq]), g_wq + hh * HID + (kc) + kq);      \
            }                                                                      \
        } while (0)

    LFILL(0, 0);   CP_COMMIT();
    LFILL(1, LCH); CP_COMMIT();

    for (int c = 0; c < HID / LCH; c++) {
        if (c + 2 < HID / LCH) {
            int st = (c + 2) % 3;
            int kc = (c + 2) * LCH;
            LFILL(st, kc);
        }
        CP_COMMIT();
        CP_WAIT2();
        __syncthreads();

        int buf = c % 3;
        const float* r0 = hsm + (buf * 256 + tid) * HP;
        const float* r1 = hsm + (buf * 256 + tid + 128) * HP;
        #pragma unroll
        for (int k = 0; k < LCH; k += 8) {
            ulonglong2 a0 = *(const ulonglong2*)(r0 + k);
            ulonglong2 b0 = *(const ulonglong2*)(r0 + k + 4);
            ulonglong2 a1 = *(const ulonglong2*)(r1 + k);
            ulonglong2 b1 = *(const ulonglong2*)(r1 + k + 4);
            #pragma unroll
            for (int h = 0; h < NHEADS; h++) {
                ulonglong2 w0 = *(const ulonglong2*)&wq_s[buf][h][k];
                ulonglong2 w1 = *(const ulonglong2*)&wq_s[buf][h][k + 4];
                FMA2(acc0[h], a0.x, w0.x);
                FMA2(acc0[h], a0.y, w0.y);
                FMA2(acc0[h], b0.x, w1.x);
                FMA2(acc0[h], b0.y, w1.y);
                FMA2(acc1[h], a1.x, w0.x);
                FMA2(acc1[h], a1.y, w0.y);
                FMA2(acc1[h], b1.x, w1.x);
                FMA2(acc1[h], b1.y, w1.y);
            }
        }
        __syncthreads();
    }

    size_t jA = (size_t)blockIdx.x * 256 + tid;
    size_t jB = jA + 128;
    int bA = (int)(jA >> 11), ja = (int)(jA & 2047);
    int bB = (int)(jB >> 11), jb = (int)(jB & 2047);
    #pragma unroll
    for (int h = 0; h < NHEADS; h++) {
        float cc = g_c[h];
        g_logits[((size_t)(bA * NHEADS + h)) * TT + ja] = f2_lo(acc0[h]) + f2_hi(acc0[h]) + cc;
        g_logits[((size_t)(bB * NHEADS + h)) * TT + jb] = f2_lo(acc1[h]) + f2_hi(acc1[h]) + cc;
    }
}

// ---------------- kernel 3: softmax (in-place) ----------------
__global__ void __launch_bounds__(256) k_softmax(const int* __restrict__ mask) {
    int bh = blockIdx.x;
    int b  = bh >> 4;
    float* row = g_logits + (size_t)bh * TT;
    const int* mrow = mask + (size_t)b * TT;
    int tid = threadIdx.x;

    float x[8];
    float mx = -1e30f;
    #pragma unroll
    for (int r = 0; r < 8; r++) {
        int j = tid + r * 256;
        float v = row[j];
        if (mrow[j] == 0) v = -1e30f;
        x[r] = v;
        mx = fmaxf(mx, v);
    }
    __shared__ float red[8];
    #pragma unroll
    for (int o = 16; o; o >>= 1) mx = fmaxf(mx, __shfl_xor_sync(0xffffffffu, mx, o));
    if ((tid & 31) == 0) red[tid >> 5] = mx;
    __syncthreads();
    mx = red[0];
    #pragma unroll
    for (int w = 1; w < 8; w++) mx = fmaxf(mx, red[w]);

    float sum = 0.f;
    #pragma unroll
    for (int r = 0; r < 8; r++) { float e = __expf(x[r] - mx); x[r] = e; sum += e; }
    #pragma unroll
    for (int o = 16; o; o >>= 1) sum += __shfl_xor_sync(0xffffffffu, sum, o);
    __syncthreads();
    if ((tid & 31) == 0) red[tid >> 5] = sum;
    __syncthreads();
    sum = red[0] + red[1] + red[2] + red[3] + red[4] + red[5] + red[6] + red[7];
    float inv = __fdividef(1.f, sum);
    #pragma unroll
    for (int r = 0; r < 8; r++) row[tid + r * 256] = x[r] * inv;
}

// ---------------- kernel 4: pool via tensor cores (tf32x2 compensated) ----------------
// CTA = (i-chunk of 128, b). Per b: D[16h, 128i] = attn[16h,2048j] @ hid[2048j,1024i].
// mma.sync.m16n8k8 tf32, A = attn (row-major frag), B = hid (col-major frag).
// Each fp32 split hi/lo (tf32x2): D += ah*bh + ah*bl + al*bh (al*bl ~2e-7, dropped).
// SMEM pitches: B 136 (bank 8j+i, conflict-free), A 20 (bank 20h+j, conflict-free).
// Double-buffered 16-j stages, LDG->cvt->STS staged two ahead. No partials.
#define BP 136
__global__ void __launch_bounds__(256) k_pool(const float* __restrict__ hid) {
    __shared__ unsigned bsm[2 * 2 * 16 * BP];          // [stage][hi/lo][j16][i128 pitch136]
    __shared__ unsigned ash[2][2][16][HP];             // [stage][hi/lo][h16][j16 pitch20]
    int b   = blockIdx.y;
    int i0  = blockIdx.x * 128;
    int tid = threadIdx.x;
    int l   = tid & 31, wid = tid >> 5;
    int grp = l >> 2,  thr = l & 3;

    // staging coords: B rows (16 j x 128 i, 8 floats/thread), A (16h x 16j, 1/thread)
    int sj = tid >> 4;            // j row 0..15
    int si = (tid & 15) * 8;      // i offset
    int ahh = tid >> 4;           // h for A staging
    int aj  = tid & 15;           // j for A staging

    float4 hx0, hx1;
    float  ax;

    #define PLOAD(s) do {                                                          \
        const float* hr = hid + ((size_t)b * TT + (s) * 16 + sj) * HID + i0 + si;  \
        hx0 = *(const float4*)hr;                                                  \
        hx1 = *(const float4*)(hr + 4);                                            \
        ax  = g_logits[((size_t)(b * NHEADS + ahh)) * TT + (s) * 16 + aj];         \
    } while (0)

    #define PSTS(st) do {                                                          \
        unsigned* dh = &bsm[(((st) * 2 + 0) * 16 + sj) * BP + si];                 \
        unsigned* dl = &bsm[(((st) * 2 + 1) * 16 + sj) * BP + si];                 \
        uint4 vh, vl;                                                              \
        vh.x = cvt_tf32(hx0.x); vl.x = cvt_tf32(hx0.x - __uint_as_float(vh.x));    \
        vh.y = cvt_tf32(hx0.y); vl.y = cvt_tf32(hx0.y - __uint_as_float(vh.y));    \
        vh.z = cvt_tf32(hx0.z); vl.z = cvt_tf32(hx0.z - __uint_as_float(vh.z));    \
        vh.w = cvt_tf32(hx0.w); vl.w = cvt_tf32(hx0.w - __uint_as_float(vh.w));    \
        *(uint4*)dh = vh; *(uint4*)dl = vl;                                        \
        vh.x = cvt_tf32(hx1.x); vl.x = cvt_tf32(hx1.x - __uint_as_float(vh.x));    \
        vh.y = cvt_tf32(hx1.y); vl.y = cvt_tf32(hx1.y - __uint_as_float(vh.y));    \
        vh.z = cvt_tf32(hx1.z); vl.z = cvt_tf32(hx1.z - __uint_as_float(vh.z));    \
        vh.w = cvt_tf32(hx1.w); vl.w = cvt_tf32(hx1.w - __uint_as_float(vh.w));    \
        *(uint4*)(dh + 4) = vh; *(uint4*)(dl + 4) = vl;                            \
        unsigned aih = cvt_tf32(ax);                                               \
        ash[st][0][ahh][aj] = aih;                                                 \
        ash[st][1][ahh][aj] = cvt_tf32(ax - __uint_as_float(aih));                 \
    } while (0)

    float d00 = 0.f, d01 = 0.f, d02 = 0.f, d03 = 0.f;
    float d10 = 0.f, d11 = 0.f, d12 = 0.f, d13 = 0.f;

    PLOAD(0);
    PSTS(0);
    PLOAD(1);
    __syncthreads();

    for (int s = 0; s < 128; s++) {
        if (s + 1 < 128) PSTS((s + 1) & 1);
        if (s + 2 < 128) PLOAD(s + 2);

        int st = s & 1;
        const unsigned* bh = &bsm[((st * 2 + 0) * 16) * BP];
        const unsigned* bl = &bsm[((st * 2 + 1) * 16) * BP];
        #pragma unroll
        for (int ks = 0; ks < 2; ks++) {
            int jb = ks * 8;
            unsigned a0h = ash[st][0][grp][jb + thr];
            unsigned a1h = ash[st][0][grp + 8][jb + thr];
            unsigned a2h = ash[st][0][grp][jb + thr + 4];
            unsigned a3h = ash[st][0][grp + 8][jb + thr + 4];
            unsigned a0l = ash[st][1][grp][jb + thr];
            unsigned a1l = ash[st][1][grp + 8][jb + thr];
            unsigned a2l = ash[st][1][grp][jb + thr + 4];
            unsigned a3l = ash[st][1][grp + 8][jb + thr + 4];

            int ib = wid * 16 + grp;
            unsigned b0h = bh[(jb + thr) * BP + ib];
            unsigned b1h = bh[(jb + thr + 4) * BP + ib];
            unsigned b0l = bl[(jb + thr) * BP + ib];
            unsigned b1l = bl[(jb + thr + 4) * BP + ib];
            MMA8(d00, d01, d02, d03, a0h, a1h, a2h, a3h, b0h, b1h);
            MMA8(d00, d01, d02, d03, a0h, a1h, a2h, a3h, b0l, b1l);
            MMA8(d00, d01, d02, d03, a0l, a1l, a2l, a3l, b0h, b1h);

            unsigned c0h = bh[(jb + thr) * BP + ib + 8];
            unsigned c1h = bh[(jb + thr + 4) * BP + ib + 8];
            unsigned c0l = bl[(jb + thr) * BP + ib + 8];
            unsigned c1l = bl[(jb + thr + 4) * BP + ib + 8];
            MMA8(d10, d11, d12, d13, a0h, a1h, a2h, a3h, c0h, c1h);
            MMA8(d10, d11, d12, d13, a0h, a1h, a2h, a3h, c0l, c1l);
            MMA8(d10, d11, d12, d13, a0l, a1l, a2l, a3l, c0h, c1h);
        }
        __syncthreads();
    }

    int iO = i0 + wid * 16 + 2 * thr;
    float* p0 = g_pooled + ((size_t)(b * NHEADS + grp)) * HID;
    float* p8 = g_pooled + ((size_t)(b * NHEADS + grp + 8)) * HID;
    *(float2*)(p0 + iO)     = make_float2(d00, d01);
    *(float2*)(p8 + iO)     = make_float2(d02, d03);
    *(float2*)(p0 + iO + 8) = make_float2(d10, d11);
    *(float2*)(p8 + iO + 8) = make_float2(d12, d13);
}

// ---------------- kernel 5: per-head V projection with weight-tile reuse ----------------
__global__ void __launch_bounds__(256) k_vproj(const float* __restrict__ kvw,
                                               const float* __restrict__ kvb) {
    int h  = blockIdx.x;
    int dg = blockIdx.y;            // 0/1 -> d-half
    __shared__ float p_s[32][64];   // [b][i]
    __shared__ float w_s[64 * 32];  // [i][d] linear
    int tid = threadIdx.x;
    int d   = tid & 31;
    int bg  = tid >> 5;             // warp id = b-group (4 b each)

    float acc[4] = {0.f, 0.f, 0.f, 0.f};

    for (int c = 0; c < 16; c++) {
        int i0 = c * 64;
        __syncthreads();
        #pragma unroll
        for (int p = 0; p < 2; p++) {
            int o4 = (p * 256 + tid) * 4;
            int i  = o4 >> 5;
            int cc = o4 & 31;
            *(float4*)&w_s[o4] =
                *(const float4*)(kvw + (size_t)(i0 + i) * (2 * HID) + HID + h * 64 + dg * 32 + cc);
        }
        #pragma unroll
        for (int p = 0; p < 2; p++) {
            int idx = p * 256 + tid;
            int b   = idx >> 4;
            int c4  = (idx & 15) * 4;
            *(float4*)&p_s[b][c4] =
                *(const float4*)(g_pooled + ((size_t)b * NHEADS + h) * HID + i0 + c4);
        }
        __syncthreads();

        #pragma unroll 8
        for (int i = 0; i < 64; i++) {
            float w = w_s[i * 32 + d];
            #pragma unroll
            for (int bb = 0; bb < 4; bb++)
                acc[bb] += p_s[bg * 4 + bb][i] * w;
        }
    }

    float bias = kvb[HID + h * 64 + dg * 32 + d];
    #pragma unroll
    for (int bb = 0; bb < 4; bb++) {
        int b = bg * 4 + bb;
        g_outv[b * HID + h * 64 + dg * 32 + d] = acc[bb] + bias;
    }
}

// ---------------- kernel 6: final GEMM [32,1024] x [1024,1024], c-sliced ----------------
__global__ void __launch_bounds__(256) k_final(const float* __restrict__ outw) {
    int p0 = blockIdx.x * 128;
    int c0 = blockIdx.y * 64;
    __shared__ float outv_s[32][64];
    int tid = threadIdx.x;
    for (int t = tid; t < 32 * 64; t += 256) {
        int bb2 = t >> 6;
        int cc  = t & 63;
        outv_s[bb2][cc] = g_outv[bb2 * HID + c0 + cc];
    }
    __syncthreads();

    int p   = tid & 127;
    int bh2 = tid >> 7;
    float acc[16];
    #pragma unroll
    for (int n = 0; n < 16; n++) acc[n] = 0.f;

    #pragma unroll 4
    for (int cc = 0; cc < 64; cc++) {
        float w = __ldg(outw + (size_t)(c0 + cc) * 1024 + p0 + p);
        #pragma unroll
        for (int n = 0; n < 16; n++) acc[n] += outv_s[bh2 * 16 + n][cc] * w;
    }
    #pragma unroll
    for (int n = 0; n < 16; n++)
        g_fpart[((size_t)blockIdx.y * BB + bh2 * 16 + n) * 1024 + p0 + p] = acc[n];
}

__global__ void k_finred(const float* __restrict__ outb, float* __restrict__ out) {
    int idx = blockIdx.x * 256 + threadIdx.x;
    int b = idx >> 10;
    int p = idx & 1023;
    float s = outb[p];
    #pragma unroll
    for (int cs = 0; cs < 16; cs++) s += g_fpart[((size_t)cs * BB + b) * 1024 + p];
    out[idx] = s;
}

// ---------------- launch ----------------
extern "C" void kernel_launch(void* const* d_in, const int* in_sizes, int n_in,
                              void* d_out, int out_size) {
    const float* hid  = (const float*)d_in[0];
    const int*   mask = (const int*)  d_in[1];
    const float* kvw  = (const float*)d_in[2];
    const float* kvb  = (const float*)d_in[3];
    const float* outw = (const float*)d_in[4];
    const float* outb = (const float*)d_in[5];
    const float* q    = (const float*)d_in[6];
    float* out = (float*)d_out;

    cudaFuncSetAttribute(k_logits, cudaFuncAttributeMaxDynamicSharedMemorySize, 61440);

    k_wq     <<<2048, 256>>>(q, kvw, kvb);
    k_logits <<<256, 128, 61440>>>(hid);
    k_softmax<<<512, 256>>>(mask);
    k_pool   <<<dim3(8, 32), 256>>>(hid);
    k_vproj  <<<dim3(16, 2), 256>>>(kvw, kvb);
    k_final  <<<dim3(8, 16), 256>>>(outw);
    k_finred <<<128, 256>>>(outb, out);
}

// round 10
// speedup vs baseline: 1.1535x; 1.1535x over previous
#include <cuda_runtime.h>
#include <cstdint>

#define NHEADS 16
#define HID    1024
#define TT     2048
#define BB     32

typedef unsigned long long ull;

// ---------------- device scratch (no allocations allowed) ----------------
__device__ float g_wq[NHEADS * HID];
__device__ float g_c[NHEADS];
__device__ float g_logits[BB * NHEADS * TT];          // reused in-place as attn
__device__ float g_partial[16 * BB * NHEADS * HID];   // pool partials
__device__ float g_pooled[BB * NHEADS * HID];         // reduced pooled hidden
__device__ float g_outv[BB * HID];
__device__ float g_fpart[16 * BB * HID];

#define FMA2(c, a, b) asm("fma.rn.f32x2 %0, %1, %2, %0;" : "+l"(c) : "l"(a), "l"(b))
static __device__ __forceinline__ float f2_lo(ull v) { return __uint_as_float((unsigned)(v & 0xffffffffull)); }
static __device__ __forceinline__ float f2_hi(ull v) { return __uint_as_float((unsigned)(v >> 32)); }

static __device__ __forceinline__ unsigned smaddr(const void* p) {
    return (unsigned)__cvta_generic_to_shared(p);
}
#define CP16(dst, src)  asm volatile("cp.async.cg.shared.global [%0], [%1], 16;" :: "r"(dst), "l"(src))
#define CP_COMMIT()     asm volatile("cp.async.commit_group;" ::: "memory")
#define CP_WAIT2()      asm volatile("cp.async.wait_group 2;" ::: "memory")

// ---------------- kernel 1: fold query into kv_w (k half) ----------------
__global__ void k_wq(const float* __restrict__ q,
                     const float* __restrict__ kvw,
                     const float* __restrict__ kvb) {
    int w = blockIdx.x * (blockDim.x >> 5) + (threadIdx.x >> 5);
    int lane = threadIdx.x & 31;
    if (w < NHEADS * HID) {
        int h = w & (NHEADS - 1);
        int i = w >> 4;
        const float* wr = kvw + (size_t)i * (2 * HID) + h * 64;
        const float* qr = q + h * 64;
        float s = qr[lane] * wr[lane] + qr[lane + 32] * wr[lane + 32];
        #pragma unroll
        for (int o = 16; o; o >>= 1) s += __shfl_xor_sync(0xffffffffu, s, o);
        if (lane == 0) g_wq[h * HID + i] = 0.125f * s;
    }
    if (blockIdx.x == 0 && threadIdx.x < NHEADS) {
        int h = threadIdx.x;
        float s = 0.f;
        for (int d = 0; d < 64; d++) s += q[h * 64 + d] * kvb[h * 64 + d];
        g_c[h] = 0.125f * s;
    }
}

// ---------------- kernel 2: logits (measured-best: 3-stage, 2 rows/thread) ----------------
#define LCH 16
#define HP  20
__global__ void __launch_bounds__(128) k_logits(const float* __restrict__ hid) {
    extern __shared__ __align__(16) float hsm[];        // [3][256][20]
    __shared__ __align__(16) float wq_s[3][NHEADS][LCH];
    int tid = threadIdx.x;
    const float* hblk = hid + (size_t)blockIdx.x * 256 * HID;

    ull acc0[NHEADS], acc1[NHEADS];
    #pragma unroll
    for (int h = 0; h < NHEADS; h++) { acc0[h] = 0ull; acc1[h] = 0ull; }

    #define LFILL(st, kc)                                                          \
        do {                                                                       \
            _Pragma("unroll")                                                      \
            for (int p = 0; p < 8; p++) {                                          \
                int idx = p * 128 + tid;                                           \
                int row = idx >> 2;                                                \
                int q4  = (idx & 3) * 4;                                           \
                CP16(smaddr(hsm + ((st) * 256 + row) * HP + q4),                   \
                     hblk + (size_t)row * HID + (kc) + q4);                        \
            }                                                                      \
            if (tid < 64) {                                                        \
                int hh = tid >> 2;                                                 \
                int kq = (tid & 3) * 4;                                            \
                CP16(smaddr(&wq_s[st][hh][kq]), g_wq + hh * HID + (kc) + kq);      \
            }                                                                      \
        } while (0)

    LFILL(0, 0);   CP_COMMIT();
    LFILL(1, LCH); CP_COMMIT();

    for (int c = 0; c < HID / LCH; c++) {
        if (c + 2 < HID / LCH) {
            int st = (c + 2) % 3;
            int kc = (c + 2) * LCH;
            LFILL(st, kc);
        }
        CP_COMMIT();
        CP_WAIT2();
        __syncthreads();

        int buf = c % 3;
        const float* r0 = hsm + (buf * 256 + tid) * HP;
        const float* r1 = hsm + (buf * 256 + tid + 128) * HP;
        #pragma unroll
        for (int k = 0; k < LCH; k += 8) {
            ulonglong2 a0 = *(const ulonglong2*)(r0 + k);
            ulonglong2 b0 = *(const ulonglong2*)(r0 + k + 4);
            ulonglong2 a1 = *(const ulonglong2*)(r1 + k);
            ulonglong2 b1 = *(const ulonglong2*)(r1 + k + 4);
            #pragma unroll
            for (int h = 0; h < NHEADS; h++) {
                ulonglong2 w0 = *(const ulonglong2*)&wq_s[buf][h][k];
                ulonglong2 w1 = *(const ulonglong2*)&wq_s[buf][h][k + 4];
                FMA2(acc0[h], a0.x, w0.x);
                FMA2(acc0[h], a0.y, w0.y);
                FMA2(acc0[h], b0.x, w1.x);
                FMA2(acc0[h], b0.y, w1.y);
                FMA2(acc1[h], a1.x, w0.x);
                FMA2(acc1[h], a1.y, w0.y);
                FMA2(acc1[h], b1.x, w1.x);
                FMA2(acc1[h], b1.y, w1.y);
            }
        }
        __syncthreads();
    }

    size_t jA = (size_t)blockIdx.x * 256 + tid;
    size_t jB = jA + 128;
    int bA = (int)(jA >> 11), ja = (int)(jA & 2047);
    int bB = (int)(jB >> 11), jb = (int)(jB & 2047);
    #pragma unroll
    for (int h = 0; h < NHEADS; h++) {
        float cc = g_c[h];
        g_logits[((size_t)(bA * NHEADS + h)) * TT + ja] = f2_lo(acc0[h]) + f2_hi(acc0[h]) + cc;
        g_logits[((size_t)(bB * NHEADS + h)) * TT + jb] = f2_lo(acc1[h]) + f2_hi(acc1[h]) + cc;
    }
}

// ---------------- kernel 3: softmax (in-place) ----------------
__global__ void __launch_bounds__(256) k_softmax(const int* __restrict__ mask) {
    int bh = blockIdx.x;
    int b  = bh >> 4;
    float* row = g_logits + (size_t)bh * TT;
    const int* mrow = mask + (size_t)b * TT;
    int tid = threadIdx.x;

    float x[8];
    float mx = -1e30f;
    #pragma unroll
    for (int r = 0; r < 8; r++) {
        int j = tid + r * 256;
        float v = row[j];
        if (mrow[j] == 0) v = -1e30f;
        x[r] = v;
        mx = fmaxf(mx, v);
    }
    __shared__ float red[8];
    #pragma unroll
    for (int o = 16; o; o >>= 1) mx = fmaxf(mx, __shfl_xor_sync(0xffffffffu, mx, o));
    if ((tid & 31) == 0) red[tid >> 5] = mx;
    __syncthreads();
    mx = red[0];
    #pragma unroll
    for (int w = 1; w < 8; w++) mx = fmaxf(mx, red[w]);

    float sum = 0.f;
    #pragma unroll
    for (int r = 0; r < 8; r++) { float e = __expf(x[r] - mx); x[r] = e; sum += e; }
    #pragma unroll
    for (int o = 16; o; o >>= 1) sum += __shfl_xor_sync(0xffffffffu, sum, o);
    __syncthreads();
    if ((tid & 31) == 0) red[tid >> 5] = sum;
    __syncthreads();
    sum = red[0] + red[1] + red[2] + red[3] + red[4] + red[5] + red[6] + red[7];
    float inv = __fdividef(1.f, sum);
    #pragma unroll
    for (int r = 0; r < 8; r++) row[tid + r * 256] = x[r] * inv;
}

// ---------------- kernel 4: pool (measured-best R4 version, unchanged) ----------------
__global__ void __launch_bounds__(256) k_pool(const float* __restrict__ hid) {
    extern __shared__ __align__(16) float hsm2[];        // [3][8][1024]
    __shared__ __align__(16) ull attn_s[128][NHEADS];
    int slice = blockIdx.x;       // 16 slices of 128 j
    int b     = blockIdx.y;
    int j0    = slice * 128;
    int tid   = threadIdx.x;

    const float* hbase = hid + ((size_t)b * TT + j0) * HID;

    #pragma unroll
    for (int st = 0; st < 2; st++) {
        float* dstb = hsm2 + st * 8192;
        const float* srcb = hbase + (size_t)st * 8 * HID;
        #pragma unroll
        for (int p = 0; p < 8; p++) {
            int idx = p * 256 + tid;
            int row = idx >> 8;
            int col = (idx & 255) * 4;
            CP16(smaddr(dstb + row * 1024 + col), srcb + (size_t)row * HID + col);
        }
        CP_COMMIT();
    }

    #pragma unroll
    for (int t = 0; t < 8; t++) {
        int idx  = t * 256 + tid;
        int jloc = idx & 127;
        int h    = idx >> 7;
        float a = g_logits[((size_t)(b * NHEADS + h)) * TT + j0 + jloc];
        unsigned u = __float_as_uint(a);
        attn_s[jloc][h] = ((ull)u << 32) | u;
    }

    int i0 = tid * 4;
    ull acc[32];
    #pragma unroll
    for (int t = 0; t < 32; t++) acc[t] = 0ull;

    for (int s = 0; s < 16; s++) {
        if (s + 2 < 16) {
            float* dstb = hsm2 + ((s + 2) % 3) * 8192;
            const float* srcb = hbase + (size_t)(s + 2) * 8 * HID;
            #pragma unroll
            for (int p = 0; p < 8; p++) {
                int idx = p * 256 + tid;
                int row = idx >> 8;
                int col = (idx & 255) * 4;
                CP16(smaddr(dstb + row * 1024 + col), srcb + (size_t)row * HID + col);
            }
        }
        CP_COMMIT();
        CP_WAIT2();
        __syncthreads();

        const float* buf = hsm2 + (s % 3) * 8192;
        #pragma unroll
        for (int jj = 0; jj < 8; jj++) {
            int j = s * 8 + jj;
            ulonglong2 u0 = *(const ulonglong2*)(buf + jj * 1024 + i0);
            #pragma unroll
            for (int p = 0; p < 8; p++) {
                ulonglong2 ap = *(const ulonglong2*)&attn_s[j][2 * p];
                FMA2(acc[4 * p + 0], ap.x, u0.x);
                FMA2(acc[4 * p + 1], ap.x, u0.y);
                FMA2(acc[4 * p + 2], ap.y, u0.x);
                FMA2(acc[4 * p + 3], ap.y, u0.y);
            }
        }
        __syncthreads();
    }

    float* pbase = g_partial + (((size_t)slice * BB + b) * NHEADS) * HID + i0;
    #pragma unroll
    for (int h = 0; h < NHEADS; h++) {
        float4 o;
        o.x = f2_lo(acc[2 * h]);     o.y = f2_hi(acc[2 * h]);
        o.z = f2_lo(acc[2 * h + 1]); o.w = f2_hi(acc[2 * h + 1]);
        *(float4*)(pbase + (size_t)h * HID) = o;
    }
}

// ---------------- kernel 5a: reduce 16 pool slices -> pooled (streaming) ----------------
__global__ void __launch_bounds__(256) k_reduce() {
    int idx = blockIdx.x * 256 + threadIdx.x;   // 131072 float4
    const float4* p = (const float4*)g_partial;
    float4 s = p[idx];
    #pragma unroll
    for (int sl = 1; sl < 16; sl++) {
        float4 v = p[(size_t)sl * 131072 + idx];
        s.x += v.x; s.y += v.y; s.z += v.z; s.w += v.w;
    }
    ((float4*)g_pooled)[idx] = s;
}

// ---------------- kernel 5b: per-head V projection with weight-tile reuse ----------------
__global__ void __launch_bounds__(256) k_vproj(const float* __restrict__ kvw,
                                               const float* __restrict__ kvb) {
    int h  = blockIdx.x;
    int dg = blockIdx.y;            // 0/1 -> d-half
    __shared__ float p_s[32][64];   // [b][i]
    __shared__ float w_s[64 * 32];  // [i][d] linear
    int tid = threadIdx.x;
    int d   = tid & 31;
    int bg  = tid >> 5;             // warp id = b-group (4 b each)

    float acc[4] = {0.f, 0.f, 0.f, 0.f};

    for (int c = 0; c < 16; c++) {
        int i0 = c * 64;
        __syncthreads();
        #pragma unroll
        for (int p = 0; p < 2; p++) {
            int o4 = (p * 256 + tid) * 4;
            int i  = o4 >> 5;
            int cc = o4 & 31;
            *(float4*)&w_s[o4] =
                *(const float4*)(kvw + (size_t)(i0 + i) * (2 * HID) + HID + h * 64 + dg * 32 + cc);
        }
        #pragma unroll
        for (int p = 0; p < 2; p++) {
            int idx = p * 256 + tid;
            int b   = idx >> 4;
            int c4  = (idx & 15) * 4;
            *(float4*)&p_s[b][c4] =
                *(const float4*)(g_pooled + ((size_t)b * NHEADS + h) * HID + i0 + c4);
        }
        __syncthreads();

        #pragma unroll 8
        for (int i = 0; i < 64; i++) {
            float w = w_s[i * 32 + d];
            #pragma unroll
            for (int bb = 0; bb < 4; bb++)
                acc[bb] += p_s[bg * 4 + bb][i] * w;
        }
    }

    float bias = kvb[HID + h * 64 + dg * 32 + d];
    #pragma unroll
    for (int bb = 0; bb < 4; bb++) {
        int b = bg * 4 + bb;
        g_outv[b * HID + h * 64 + dg * 32 + d] = acc[bb] + bias;
    }
}

// ---------------- kernel 6: final GEMM [32,1024] x [1024,1024], c-sliced ----------------
__global__ void __launch_bounds__(256) k_final(const float* __restrict__ outw) {
    int p0 = blockIdx.x * 128;
    int c0 = blockIdx.y * 64;
    __shared__ float outv_s[32][64];
    int tid = threadIdx.x;
    for (int t = tid; t < 32 * 64; t += 256) {
        int bb2 = t >> 6;
        int cc  = t & 63;
        outv_s[bb2][cc] = g_outv[bb2 * HID + c0 + cc];
    }
    __syncthreads();

    int p   = tid & 127;
    int bh2 = tid >> 7;
    float acc[16];
    #pragma unroll
    for (int n = 0; n < 16; n++) acc[n] = 0.f;

    #pragma unroll 4
    for (int cc = 0; cc < 64; cc++) {
        float w = __ldg(outw + (size_t)(c0 + cc) * 1024 + p0 + p);
        #pragma unroll
        for (int n = 0; n < 16; n++) acc[n] += outv_s[bh2 * 16 + n][cc] * w;
    }
    #pragma unroll
    for (int n = 0; n < 16; n++)
        g_fpart[((size_t)blockIdx.y * BB + bh2 * 16 + n) * 1024 + p0 + p] = acc[n];
}

__global__ void k_finred(const float* __restrict__ outb, float* __restrict__ out) {
    int idx = blockIdx.x * 256 + threadIdx.x;
    int b = idx >> 10;
    int p = idx & 1023;
    float s = outb[p];
    #pragma unroll
    for (int cs = 0; cs < 16; cs++) s += g_fpart[((size_t)cs * BB + b) * 1024 + p];
    out[idx] = s;
}

// ---------------- launch ----------------
extern "C" void kernel_launch(void* const* d_in, const int* in_sizes, int n_in,
                              void* d_out, int out_size) {
    const float* hid  = (const float*)d_in[0];
    const int*   mask = (const int*)  d_in[1];
    const float* kvw  = (const float*)d_in[2];
    const float* kvb  = (const float*)d_in[3];
    const float* outw = (const float*)d_in[4];
    const float* outb = (const float*)d_in[5];
    const float* q    = (const float*)d_in[6];
    float* out = (float*)d_out;

    cudaFuncSetAttribute(k_logits, cudaFuncAttributeMaxDynamicSharedMemorySize, 61440);
    cudaFuncSetAttribute(k_pool,   cudaFuncAttributeMaxDynamicSharedMemorySize, 98304);

    k_wq     <<<2048, 256>>>(q, kvw, kvb);
    k_logits <<<256, 128, 61440>>>(hid);
    k_softmax<<<512, 256>>>(mask);
    k_pool   <<<dim3(16, 32), 256, 98304>>>(hid);
    k_reduce <<<512, 256>>>();
    k_vproj  <<<dim3(16, 2), 256>>>(kvw, kvb);
    k_final  <<<dim3(8, 16), 256>>>(outw);
    k_finred <<<128, 256>>>(outb, out);
}

// round 11
// speedup vs baseline: 1.2992x; 1.1263x over previous
#include <cuda_runtime.h>
#include <cstdint>

#define NHEADS 16
#define HID    1024
#define TT     2048
#define BB     32

typedef unsigned long long ull;

// ---------------- device scratch (no allocations allowed) ----------------
__device__ float g_wqh[NHEADS * HID];                 // tf32-hi of folded q @ kv_w
__device__ float g_wql[NHEADS * HID];                 // tf32-lo residual
__device__ float g_c[NHEADS];
__device__ float g_logits[BB * NHEADS * TT];          // reused in-place as attn
__device__ float g_partial[16 * BB * NHEADS * HID];   // pool partials
__device__ float g_pooled[BB * NHEADS * HID];         // reduced pooled hidden
__device__ float g_outv[BB * HID];
__device__ float g_fpart[16 * BB * HID];

#define FMA2(c, a, b) asm("fma.rn.f32x2 %0, %1, %2, %0;" : "+l"(c) : "l"(a), "l"(b))
static __device__ __forceinline__ float f2_lo(ull v) { return __uint_as_float((unsigned)(v & 0xffffffffull)); }
static __device__ __forceinline__ float f2_hi(ull v) { return __uint_as_float((unsigned)(v >> 32)); }

static __device__ __forceinline__ unsigned smaddr(const void* p) {
    return (unsigned)__cvta_generic_to_shared(p);
}
#define CP16(dst, src)  asm volatile("cp.async.cg.shared.global [%0], [%1], 16;" :: "r"(dst), "l"(src))
#define CP_COMMIT()     asm volatile("cp.async.commit_group;" ::: "memory")
#define CP_WAIT2()      asm volatile("cp.async.wait_group 2;" ::: "memory")

static __device__ __forceinline__ unsigned cvt_tf32(float x) {
    unsigned r;
    asm("cvt.rna.tf32.f32 %0, %1;" : "=r"(r) : "f"(x));
    return r;
}
#define MMA8(d0, d1, d2, d3, a0, a1, a2, a3, b0, b1)                     \
    asm("mma.sync.aligned.m16n8k8.row.col.f32.tf32.tf32.f32 "            \
        "{%0,%1,%2,%3},{%4,%5,%6,%7},{%8,%9},{%0,%1,%2,%3};"             \
        : "+f"(d0), "+f"(d1), "+f"(d2), "+f"(d3)                         \
        : "r"(a0), "r"(a1), "r"(a2), "r"(a3), "r"(b0), "r"(b1))

// ---------------- kernel 1: fold query into kv_w (k half), emit tf32 hi/lo ----------------
__global__ void k_wq(const float* __restrict__ q,
                     const float* __restrict__ kvw,
                     const float* __restrict__ kvb) {
    int w = blockIdx.x * (blockDim.x >> 5) + (threadIdx.x >> 5);
    int lane = threadIdx.x & 31;
    if (w < NHEADS * HID) {
        int h = w & (NHEADS - 1);
        int i = w >> 4;
        const float* wr = kvw + (size_t)i * (2 * HID) + h * 64;
        const float* qr = q + h * 64;
        float s = qr[lane] * wr[lane] + qr[lane + 32] * wr[lane + 32];
        #pragma unroll
        for (int o = 16; o; o >>= 1) s += __shfl_xor_sync(0xffffffffu, s, o);
        if (lane == 0) {
            float v = 0.125f * s;
            unsigned hi = cvt_tf32(v);
            g_wqh[h * HID + i] = __uint_as_float(hi);
            g_wql[h * HID + i] = __uint_as_float(cvt_tf32(v - __uint_as_float(hi)));
        }
    }
    if (blockIdx.x == 0 && threadIdx.x < NHEADS) {
        int h = threadIdx.x;
        float s = 0.f;
        for (int d = 0; d < 64; d++) s += q[h * 64 + d] * kvb[h * 64 + d];
        g_c[h] = 0.125f * s;
    }
}

// ---------------- kernel 2: logits via tensor cores ----------------
// C[256j, 16h] = hid[256j, 1024k] @ wq^T. m16n8k8 tf32; A = hid rows (hi only,
// ~1.4e-4 logit err), B = wq hi + lo (precomputed). 256 threads = 8 warps,
// warp owns 32 j (2 m-tiles). hid staged with the measured 3-stage cp.async
// ring, pitch 20 (fragment LDS banks {20g+t} all distinct -> conflict-free).
#define LCH 16
#define HP  20
__global__ void __launch_bounds__(256) k_logits(const float* __restrict__ hid) {
    extern __shared__ __align__(16) float hsm[];        // [3][256][20]
    __shared__ __align__(16) float wq_s[3][2][NHEADS][HP];  // [stage][hi/lo][h][k]
    int tid = threadIdx.x;
    int wid = tid >> 5, l = tid & 31;
    int grp = l >> 2,   thr = l & 3;
    const float* hblk = hid + (size_t)blockIdx.x * 256 * HID;

    float acc[2][2][4];
    #pragma unroll
    for (int m = 0; m < 2; m++)
        #pragma unroll
        for (int n = 0; n < 2; n++)
            #pragma unroll
            for (int r = 0; r < 4; r++) acc[m][n][r] = 0.f;

    // stage st <- k chunk kc : hid 256x16 (1024 float4, 4/thread) + wq hi/lo
    #define LFILL(st, kc)                                                          \
        do {                                                                       \
            _Pragma("unroll")                                                      \
            for (int p = 0; p < 4; p++) {                                          \
                int idx = p * 256 + tid;                                           \
                int row = idx >> 2;                                                \
                int q4  = (idx & 3) * 4;                                           \
                CP16(smaddr(hsm + ((st) * 256 + row) * HP + q4),                   \
                     hblk + (size_t)row * HID + (kc) + q4);                        \
            }                                                                      \
            if (tid < 128) {                                                       \
                int half = tid >> 6;                                               \
                int hh   = (tid >> 2) & 15;                                        \
                int kq   = (tid & 3) * 4;                                          \
                const float* src = half ? g_wql : g_wqh;                           \
                CP16(smaddr(&wq_s[st][half][hh][kq]), src + hh * HID + (kc) + kq); \
            }                                                                      \
        } while (0)

    LFILL(0, 0);   CP_COMMIT();
    LFILL(1, LCH); CP_COMMIT();

    for (int c = 0; c < HID / LCH; c++) {
        if (c + 2 < HID / LCH) {
            int st = (c + 2) % 3;
            int kc = (c + 2) * LCH;
            LFILL(st, kc);
        }
        CP_COMMIT();
        CP_WAIT2();
        __syncthreads();

        int buf = c % 3;
        const float*    hs = hsm + buf * 256 * HP;
        const unsigned* wh = (const unsigned*)&wq_s[buf][0][0][0];
        const unsigned* wl = (const unsigned*)&wq_s[buf][1][0][0];

        #pragma unroll
        for (int s = 0; s < 2; s++) {
            int k0 = s * 8;
            // B fragments (shared across both m-tiles): b0=B[thr][grp]=wq[n*8+grp][k0+thr]
            unsigned b0h0 = wh[(grp)     * HP + k0 + thr];
            unsigned b1h0 = wh[(grp)     * HP + k0 + thr + 4];
            unsigned b0h1 = wh[(8 + grp) * HP + k0 + thr];
            unsigned b1h1 = wh[(8 + grp) * HP + k0 + thr + 4];
            unsigned b0l0 = wl[(grp)     * HP + k0 + thr];
            unsigned b1l0 = wl[(grp)     * HP + k0 + thr + 4];
            unsigned b0l1 = wl[(8 + grp) * HP + k0 + thr];
            unsigned b1l1 = wl[(8 + grp) * HP + k0 + thr + 4];
            #pragma unroll
            for (int m = 0; m < 2; m++) {
                int jb = wid * 32 + m * 16;
                unsigned a0 = cvt_tf32(hs[(jb + grp)     * HP + k0 + thr]);
                unsigned a1 = cvt_tf32(hs[(jb + grp + 8) * HP + k0 + thr]);
                unsigned a2 = cvt_tf32(hs[(jb + grp)     * HP + k0 + thr + 4]);
                unsigned a3 = cvt_tf32(hs[(jb + grp + 8) * HP + k0 + thr + 4]);
                MMA8(acc[m][0][0], acc[m][0][1], acc[m][0][2], acc[m][0][3],
                     a0, a1, a2, a3, b0h0, b1h0);
                MMA8(acc[m][0][0], acc[m][0][1], acc[m][0][2], acc[m][0][3],
                     a0, a1, a2, a3, b0l0, b1l0);
                MMA8(acc[m][1][0], acc[m][1][1], acc[m][1][2], acc[m][1][3],
                     a0, a1, a2, a3, b0h1, b1h1);
                MMA8(acc[m][1][0], acc[m][1][1], acc[m][1][2], acc[m][1][3],
                     a0, a1, a2, a3, b0l1, b1l1);
            }
        }
        __syncthreads();
    }

    // epilogue: C[m16][n8] frag: c0=[grp][2thr], c1=[grp][2thr+1], c2=[grp+8][2thr], c3=[grp+8][2thr+1]
    int jg = blockIdx.x * 256 + wid * 32;
    int b  = jg >> 11;
    #pragma unroll
    for (int m = 0; m < 2; m++) {
        int j0 = (jg + m * 16 + grp) & 2047;
        #pragma unroll
        for (int n = 0; n < 2; n++) {
            int h0 = n * 8 + 2 * thr;
            g_logits[((size_t)(b * NHEADS + h0))     * TT + j0]     = acc[m][n][0] + g_c[h0];
            g_logits[((size_t)(b * NHEADS + h0 + 1)) * TT + j0]     = acc[m][n][1] + g_c[h0 + 1];
            g_logits[((size_t)(b * NHEADS + h0))     * TT + j0 + 8] = acc[m][n][2] + g_c[h0];
            g_logits[((size_t)(b * NHEADS + h0 + 1)) * TT + j0 + 8] = acc[m][n][3] + g_c[h0 + 1];
        }
    }
}

// ---------------- kernel 3: softmax (in-place) ----------------
__global__ void __launch_bounds__(256) k_softmax(const int* __restrict__ mask) {
    int bh = blockIdx.x;
    int b  = bh >> 4;
    float* row = g_logits + (size_t)bh * TT;
    const int* mrow = mask + (size_t)b * TT;
    int tid = threadIdx.x;

    float x[8];
    float mx = -1e30f;
    #pragma unroll
    for (int r = 0; r < 8; r++) {
        int j = tid + r * 256;
        float v = row[j];
        if (mrow[j] == 0) v = -1e30f;
        x[r] = v;
        mx = fmaxf(mx, v);
    }
    __shared__ float red[8];
    #pragma unroll
    for (int o = 16; o; o >>= 1) mx = fmaxf(mx, __shfl_xor_sync(0xffffffffu, mx, o));
    if ((tid & 31) == 0) red[tid >> 5] = mx;
    __syncthreads();
    mx = red[0];
    #pragma unroll
    for (int w = 1; w < 8; w++) mx = fmaxf(mx, red[w]);

    float sum = 0.f;
    #pragma unroll
    for (int r = 0; r < 8; r++) { float e = __expf(x[r] - mx); x[r] = e; sum += e; }
    #pragma unroll
    for (int o = 16; o; o >>= 1) sum += __shfl_xor_sync(0xffffffffu, sum, o);
    __syncthreads();
    if ((tid & 31) == 0) red[tid >> 5] = sum;
    __syncthreads();
    sum = red[0] + red[1] + red[2] + red[3] + red[4] + red[5] + red[6] + red[7];
    float inv = __fdividef(1.f, sum);
    #pragma unroll
    for (int r = 0; r < 8; r++) row[tid + r * 256] = x[r] * inv;
}

// ---------------- kernel 4: pool (measured-best R4 version, unchanged) ----------------
__global__ void __launch_bounds__(256) k_pool(const float* __restrict__ hid) {
    extern __shared__ __align__(16) float hsm2[];        // [3][8][1024]
    __shared__ __align__(16) ull attn_s[128][NHEADS];
    int slice = blockIdx.x;       // 16 slices of 128 j
    int b     = blockIdx.y;
    int j0    = slice * 128;
    int tid   = threadIdx.x;

    const float* hbase = hid + ((size_t)b * TT + j0) * HID;

    #pragma unroll
    for (int st = 0; st < 2; st++) {
        float* dstb = hsm2 + st * 8192;
        const float* srcb = hbase + (size_t)st * 8 * HID;
        #pragma unroll
        for (int p = 0; p < 8; p++) {
            int idx = p * 256 + tid;
            int row = idx >> 8;
            int col = (idx & 255) * 4;
            CP16(smaddr(dstb + row * 1024 + col), srcb + (size_t)row * HID + col);
        }
        CP_COMMIT();
    }

    #pragma unroll
    for (int t = 0; t < 8; t++) {
        int idx  = t * 256 + tid;
        int jloc = idx & 127;
        int h    = idx >> 7;
        float a = g_logits[((size_t)(b * NHEADS + h)) * TT + j0 + jloc];
        unsigned u = __float_as_uint(a);
        attn_s[jloc][h] = ((ull)u << 32) | u;
    }

    int i0 = tid * 4;
    ull acc[32];
    #pragma unroll
    for (int t = 0; t < 32; t++) acc[t] = 0ull;

    for (int s = 0; s < 16; s++) {
        if (s + 2 < 16) {
            float* dstb = hsm2 + ((s + 2) % 3) * 8192;
            const float* srcb = hbase + (size_t)(s + 2) * 8 * HID;
            #pragma unroll
            for (int p = 0; p < 8; p++) {
                int idx = p * 256 + tid;
                int row = idx >> 8;
                int col = (idx & 255) * 4;
                CP16(smaddr(dstb + row * 1024 + col), srcb + (size_t)row * HID + col);
            }
        }
        CP_COMMIT();
        CP_WAIT2();
        __syncthreads();

        const float* buf = hsm2 + (s % 3) * 8192;
        #pragma unroll
        for (int jj = 0; jj < 8; jj++) {
            int j = s * 8 + jj;
            ulonglong2 u0 = *(const ulonglong2*)(buf + jj * 1024 + i0);
            #pragma unroll
            for (int p = 0; p < 8; p++) {
                ulonglong2 ap = *(const ulonglong2*)&attn_s[j][2 * p];
                FMA2(acc[4 * p + 0], ap.x, u0.x);
                FMA2(acc[4 * p + 1], ap.x, u0.y);
                FMA2(acc[4 * p + 2], ap.y, u0.x);
                FMA2(acc[4 * p + 3], ap.y, u0.y);
            }
        }
        __syncthreads();
    }

    float* pbase = g_partial + (((size_t)slice * BB + b) * NHEADS) * HID + i0;
    #pragma unroll
    for (int h = 0; h < NHEADS; h++) {
        float4 o;
        o.x = f2_lo(acc[2 * h]);     o.y = f2_hi(acc[2 * h]);
        o.z = f2_lo(acc[2 * h + 1]); o.w = f2_hi(acc[2 * h + 1]);
        *(float4*)(pbase + (size_t)h * HID) = o;
    }
}

// ---------------- kernel 5a: reduce 16 pool slices -> pooled ----------------
__global__ void __launch_bounds__(256) k_reduce() {
    int idx = blockIdx.x * 256 + threadIdx.x;   // 131072 float4
    const float4* p = (const float4*)g_partial;
    float4 s = p[idx];
    #pragma unroll
    for (int sl = 1; sl < 16; sl++) {
        float4 v = p[(size_t)sl * 131072 + idx];
        s.x += v.x; s.y += v.y; s.z += v.z; s.w += v.w;
    }
    ((float4*)g_pooled)[idx] = s;
}

// ---------------- kernel 5b: per-head V projection with weight-tile reuse ----------------
__global__ void __launch_bounds__(256) k_vproj(const float* __restrict__ kvw,
                                               const float* __restrict__ kvb) {
    int h  = blockIdx.x;
    int dg = blockIdx.y;
    __shared__ float p_s[32][64];
    __shared__ float w_s[64 * 32];
    int tid = threadIdx.x;
    int d   = tid & 31;
    int bg  = tid >> 5;

    float acc[4] = {0.f, 0.f, 0.f, 0.f};

    for (int c = 0; c < 16; c++) {
        int i0 = c * 64;
        __syncthreads();
        #pragma unroll
        for (int p = 0; p < 2; p++) {
            int o4 = (p * 256 + tid) * 4;
            int i  = o4 >> 5;
            int cc = o4 & 31;
            *(float4*)&w_s[o4] =
                *(const float4*)(kvw + (size_t)(i0 + i) * (2 * HID) + HID + h * 64 + dg * 32 + cc);
        }
        #pragma unroll
        for (int p = 0; p < 2; p++) {
            int idx = p * 256 + tid;
            int b   = idx >> 4;
            int c4  = (idx & 15) * 4;
            *(float4*)&p_s[b][c4] =
                *(const float4*)(g_pooled + ((size_t)b * NHEADS + h) * HID + i0 + c4);
        }
        __syncthreads();

        #pragma unroll 8
        for (int i = 0; i < 64; i++) {
            float w = w_s[i * 32 + d];
            #pragma unroll
            for (int bb = 0; bb < 4; bb++)
                acc[bb] += p_s[bg * 4 + bb][i] * w;
        }
    }

    float bias = kvb[HID + h * 64 + dg * 32 + d];
    #pragma unroll
    for (int bb = 0; bb < 4; bb++) {
        int b = bg * 4 + bb;
        g_outv[b * HID + h * 64 + dg * 32 + d] = acc[bb] + bias;
    }
}

// ---------------- kernel 6: final GEMM [32,1024] x [1024,1024], c-sliced ----------------
__global__ void __launch_bounds__(256) k_final(const float* __restrict__ outw) {
    int p0 = blockIdx.x * 128;
    int c0 = blockIdx.y * 64;
    __shared__ float outv_s[32][64];
    int tid = threadIdx.x;
    for (int t = tid; t < 32 * 64; t += 256) {
        int bb2 = t >> 6;
        int cc  = t & 63;
        outv_s[bb2][cc] = g_outv[bb2 * HID + c0 + cc];
    }
    __syncthreads();

    int p   = tid & 127;
    int bh2 = tid >> 7;
    float acc[16];
    #pragma unroll
    for (int n = 0; n < 16; n++) acc[n] = 0.f;

    #pragma unroll 4
    for (int cc = 0; cc < 64; cc++) {
        float w = __ldg(outw + (size_t)(c0 + cc) * 1024 + p0 + p);
        #pragma unroll
        for (int n = 0; n < 16; n++) acc[n] += outv_s[bh2 * 16 + n][cc] * w;
    }
    #pragma unroll
    for (int n = 0; n < 16; n++)
        g_fpart[((size_t)blockIdx.y * BB + bh2 * 16 + n) * 1024 + p0 + p] = acc[n];
}

__global__ void k_finred(const float* __restrict__ outb, float* __restrict__ out) {
    int idx = blockIdx.x * 256 + threadIdx.x;
    int b = idx >> 10;
    int p = idx & 1023;
    float s = outb[p];
    #pragma unroll
    for (int cs = 0; cs < 16; cs++) s += g_fpart[((size_t)cs * BB + b) * 1024 + p];
    out[idx] = s;
}

// ---------------- launch ----------------
extern "C" void kernel_launch(void* const* d_in, const int* in_sizes, int n_in,
                              void* d_out, int out_size) {
    const float* hid  = (const float*)d_in[0];
    const int*   mask = (const int*)  d_in[1];
    const float* kvw  = (const float*)d_in[2];
    const float* kvb  = (const float*)d_in[3];
    const float* outw = (const float*)d_in[4];
    const float* outb = (const float*)d_in[5];
    const float* q    = (const float*)d_in[6];
    float* out = (float*)d_out;

    cudaFuncSetAttribute(k_logits, cudaFuncAttributeMaxDynamicSharedMemorySize, 61440);
    cudaFuncSetAttribute(k_pool,   cudaFuncAttributeMaxDynamicSharedMemorySize, 98304);

    k_wq     <<<2048, 256>>>(q, kvw, kvb);
    k_logits <<<256, 256, 61440>>>(hid);
    k_softmax<<<512, 256>>>(mask);
    k_pool   <<<dim3(16, 32), 256, 98304>>>(hid);
    k_reduce <<<512, 256>>>();
    k_vproj  <<<dim3(16, 2), 256>>>(kvw, kvb);
    k_final  <<<dim3(8, 16), 256>>>(outw);
    k_finred <<<128, 256>>>(outb, out);
}

// round 13
// speedup vs baseline: 1.3581x; 1.0454x over previous
#include <cuda_runtime.h>
#include <cstdint>

#define NHEADS 16
#define HID    1024
#define TT     2048
#define BB     32

typedef unsigned long long ull;

// ---------------- device scratch (no allocations allowed) ----------------
__device__ float g_wqh[NHEADS * HID];                 // tf32-hi of folded q @ kv_w
__device__ float g_wql[NHEADS * HID];                 // tf32-lo residual
__device__ float g_c[NHEADS];
__device__ float g_logits[BB * NHEADS * TT];          // logits -> attn tf32-hi (in place)
__device__ float g_attnl[BB * NHEADS * TT];           // attn tf32-lo residual
__device__ float g_pooled[BB * NHEADS * HID];         // pooled hidden
__device__ float g_outv[BB * HID];
__device__ float g_fpart[16 * BB * HID];

static __device__ __forceinline__ unsigned smaddr(const void* p) {
    return (unsigned)__cvta_generic_to_shared(p);
}
#define CP16(dst, src)  asm volatile("cp.async.cg.shared.global [%0], [%1], 16;" :: "r"(dst), "l"(src))
#define CP_COMMIT()     asm volatile("cp.async.commit_group;" ::: "memory")
#define CP_WAIT1()      asm volatile("cp.async.wait_group 1;" ::: "memory")
#define CP_WAIT2()      asm volatile("cp.async.wait_group 2;" ::: "memory")

static __device__ __forceinline__ unsigned cvt_tf32(float x) {
    unsigned r;
    asm("cvt.rna.tf32.f32 %0, %1;" : "=r"(r) : "f"(x));
    return r;
}
#define MMA8(d0, d1, d2, d3, a0, a1, a2, a3, b0, b1)                     \
    asm("mma.sync.aligned.m16n8k8.row.col.f32.tf32.tf32.f32 "            \
        "{%0,%1,%2,%3},{%4,%5,%6,%7},{%8,%9},{%0,%1,%2,%3};"             \
        : "+f"(d0), "+f"(d1), "+f"(d2), "+f"(d3)                         \
        : "r"(a0), "r"(a1), "r"(a2), "r"(a3), "r"(b0), "r"(b1))

// ---------------- kernel 1: fold query into kv_w (k half), emit tf32 hi/lo ----------------
__global__ void k_wq(const float* __restrict__ q,
                     const float* __restrict__ kvw,
                     const float* __restrict__ kvb) {
    int w = blockIdx.x * (blockDim.x >> 5) + (threadIdx.x >> 5);
    int lane = threadIdx.x & 31;
    if (w < NHEADS * HID) {
        int h = w & (NHEADS - 1);
        int i = w >> 4;
        const float* wr = kvw + (size_t)i * (2 * HID) + h * 64;
        const float* qr = q + h * 64;
        float s = qr[lane] * wr[lane] + qr[lane + 32] * wr[lane + 32];
        #pragma unroll
        for (int o = 16; o; o >>= 1) s += __shfl_xor_sync(0xffffffffu, s, o);
        if (lane == 0) {
            float v = 0.125f * s;
            unsigned hi = cvt_tf32(v);
            g_wqh[h * HID + i] = __uint_as_float(hi);
            g_wql[h * HID + i] = __uint_as_float(cvt_tf32(v - __uint_as_float(hi)));
        }
    }
    if (blockIdx.x == 0 && threadIdx.x < NHEADS) {
        int h = threadIdx.x;
        float s = 0.f;
        for (int d = 0; d < 64; d++) s += q[h * 64 + d] * kvb[h * 64 + d];
        g_c[h] = 0.125f * s;
    }
}

// ---------------- kernel 2: logits via tensor cores (measured-best R11) ----------------
#define LCH 16
#define HP  20
__global__ void __launch_bounds__(256) k_logits(const float* __restrict__ hid) {
    extern __shared__ __align__(16) float hsm[];        // [3][256][20]
    __shared__ __align__(16) float wq_s[3][2][NHEADS][HP];
    int tid = threadIdx.x;
    int wid = tid >> 5, l = tid & 31;
    int grp = l >> 2,   thr = l & 3;
    const float* hblk = hid + (size_t)blockIdx.x * 256 * HID;

    float acc[2][2][4];
    #pragma unroll
    for (int m = 0; m < 2; m++)
        #pragma unroll
        for (int n = 0; n < 2; n++)
            #pragma unroll
            for (int r = 0; r < 4; r++) acc[m][n][r] = 0.f;

    #define LFILL(st, kc)                                                          \
        do {                                                                       \
            _Pragma("unroll")                                                      \
            for (int p = 0; p < 4; p++) {                                          \
                int idx = p * 256 + tid;                                           \
                int row = idx >> 2;                                                \
                int q4  = (idx & 3) * 4;                                           \
                CP16(smaddr(hsm + ((st) * 256 + row) * HP + q4),                   \
                     hblk + (size_t)row * HID + (kc) + q4);                        \
            }                                                                      \
            if (tid < 128) {                                                       \
                int half = tid >> 6;                                               \
                int hh   = (tid >> 2) & 15;                                        \
                int kq   = (tid & 3) * 4;                                          \
                const float* src = half ? g_wql : g_wqh;                           \
                CP16(smaddr(&wq_s[st][half][hh][kq]), src + hh * HID + (kc) + kq); \
            }                                                                      \
        } while (0)

    LFILL(0, 0);   CP_COMMIT();
    LFILL(1, LCH); CP_COMMIT();

    for (int c = 0; c < HID / LCH; c++) {
        if (c + 2 < HID / LCH) {
            int st = (c + 2) % 3;
            int kc = (c + 2) * LCH;
            LFILL(st, kc);
        }
        CP_COMMIT();
        CP_WAIT2();
        __syncthreads();

        int buf = c % 3;
        const float*    hs = hsm + buf * 256 * HP;
        const unsigned* wh = (const unsigned*)&wq_s[buf][0][0][0];
        const unsigned* wl = (const unsigned*)&wq_s[buf][1][0][0];

        #pragma unroll
        for (int s = 0; s < 2; s++) {
            int k0 = s * 8;
            unsigned b0h0 = wh[(grp)     * HP + k0 + thr];
            unsigned b1h0 = wh[(grp)     * HP + k0 + thr + 4];
            unsigned b0h1 = wh[(8 + grp) * HP + k0 + thr];
            unsigned b1h1 = wh[(8 + grp) * HP + k0 + thr + 4];
            unsigned b0l0 = wl[(grp)     * HP + k0 + thr];
            unsigned b1l0 = wl[(grp)     * HP + k0 + thr + 4];
            unsigned b0l1 = wl[(8 + grp) * HP + k0 + thr];
            unsigned b1l1 = wl[(8 + grp) * HP + k0 + thr + 4];
            #pragma unroll
            for (int m = 0; m < 2; m++) {
                int jb = wid * 32 + m * 16;
                unsigned a0 = cvt_tf32(hs[(jb + grp)     * HP + k0 + thr]);
                unsigned a1 = cvt_tf32(hs[(jb + grp + 8) * HP + k0 + thr]);
                unsigned a2 = cvt_tf32(hs[(jb + grp)     * HP + k0 + thr + 4]);
                unsigned a3 = cvt_tf32(hs[(jb + grp + 8) * HP + k0 + thr + 4]);
                MMA8(acc[m][0][0], acc[m][0][1], acc[m][0][2], acc[m][0][3],
                     a0, a1, a2, a3, b0h0, b1h0);
                MMA8(acc[m][0][0], acc[m][0][1], acc[m][0][2], acc[m][0][3],
                     a0, a1, a2, a3, b0l0, b1l0);
                MMA8(acc[m][1][0], acc[m][1][1], acc[m][1][2], acc[m][1][3],
                     a0, a1, a2, a3, b0h1, b1h1);
                MMA8(acc[m][1][0], acc[m][1][1], acc[m][1][2], acc[m][1][3],
                     a0, a1, a2, a3, b0l1, b1l1);
            }
        }
        __syncthreads();
    }

    int jg = blockIdx.x * 256 + wid * 32;
    int b  = jg >> 11;
    #pragma unroll
    for (int m = 0; m < 2; m++) {
        int j0 = (jg + m * 16 + grp) & 2047;
        #pragma unroll
        for (int n = 0; n < 2; n++) {
            int h0 = n * 8 + 2 * thr;
            g_logits[((size_t)(b * NHEADS + h0))     * TT + j0]     = acc[m][n][0] + g_c[h0];
            g_logits[((size_t)(b * NHEADS + h0 + 1)) * TT + j0]     = acc[m][n][1] + g_c[h0 + 1];
            g_logits[((size_t)(b * NHEADS + h0))     * TT + j0 + 8] = acc[m][n][2] + g_c[h0];
            g_logits[((size_t)(b * NHEADS + h0 + 1)) * TT + j0 + 8] = acc[m][n][3] + g_c[h0 + 1];
        }
    }
}

// ---------------- kernel 3: softmax -> attn tf32 hi (in place) + lo ----------------
__global__ void __launch_bounds__(256) k_softmax(const int* __restrict__ mask) {
    int bh = blockIdx.x;
    int b  = bh >> 4;
    float* row = g_logits + (size_t)bh * TT;
    float* rowl = g_attnl + (size_t)bh * TT;
    const int* mrow = mask + (size_t)b * TT;
    int tid = threadIdx.x;

    float x[8];
    float mx = -1e30f;
    #pragma unroll
    for (int r = 0; r < 8; r++) {
        int j = tid + r * 256;
        float v = row[j];
        if (mrow[j] == 0) v = -1e30f;
        x[r] = v;
        mx = fmaxf(mx, v);
    }
    __shared__ float red[8];
    #pragma unroll
    for (int o = 16; o; o >>= 1) mx = fmaxf(mx, __shfl_xor_sync(0xffffffffu, mx, o));
    if ((tid & 31) == 0) red[tid >> 5] = mx;
    __syncthreads();
    mx = red[0];
    #pragma unroll
    for (int w = 1; w < 8; w++) mx = fmaxf(mx, red[w]);

    float sum = 0.f;
    #pragma unroll
    for (int r = 0; r < 8; r++) { float e = __expf(x[r] - mx); x[r] = e; sum += e; }
    #pragma unroll
    for (int o = 16; o; o >>= 1) sum += __shfl_xor_sync(0xffffffffu, sum, o);
    __syncthreads();
    if ((tid & 31) == 0) red[tid >> 5] = sum;
    __syncthreads();
    sum = red[0] + red[1] + red[2] + red[3] + red[4] + red[5] + red[6] + red[7];
    float inv = __fdividef(1.f, sum);
    #pragma unroll
    for (int r = 0; r < 8; r++) {
        int j = tid + r * 256;
        float w = x[r] * inv;
        unsigned hi = cvt_tf32(w);
        row[j]  = __uint_as_float(hi);
        rowl[j] = __uint_as_float(cvt_tf32(w - __uint_as_float(hi)));
    }
}

// ---------------- kernel 4: pool via tensor cores ----------------
// CTA = (i-chunk 128, b): C[16h,128i] = attn[16h,2048j] @ hid[2048j,128i].
// 64 stages of 32 j, 3-stage ring. Wait-first ordering -> CP_WAIT1 is the
// correct depth (stages {s, s+1} pending at the wait; wait1 completes s).
#define PBP 136
#define PAP 36
#define HID3 (3 * 32 * PBP)                 // 13056 floats
#define AH0  HID3                           // attn-hi stages
#define AL0  (HID3 + 3 * NHEADS * PAP)      // attn-lo stages
__global__ void __launch_bounds__(256) k_pool(const float* __restrict__ hid) {
    extern __shared__ __align__(16) float psm[];
    int b   = blockIdx.y;
    int i0  = blockIdx.x * 128;
    int tid = threadIdx.x;
    int wid = tid >> 5, l = tid & 31;
    int grp = l >> 2,   thr = l & 3;

    const float* hbase = hid + (size_t)b * TT * HID + i0;

    #define PFILL(st, j0)                                                          \
        do {                                                                       \
            _Pragma("unroll")                                                      \
            for (int p = 0; p < 4; p++) {                                          \
                int idx = p * 256 + tid;                                           \
                int row = idx >> 5;                                                \
                int c4  = (idx & 31) * 4;                                          \
                CP16(smaddr(psm + (st) * 32 * PBP + row * PBP + c4),               \
                     hbase + (size_t)((j0) + row) * HID + c4);                     \
            }                                                                      \
            {                                                                      \
                int half = tid >> 7;                                               \
                int hh   = (tid >> 3) & 15;                                        \
                int j4   = (tid & 7) * 4;                                          \
                const float* src = half ? g_attnl : g_logits;                      \
                int base = half ? AL0 : AH0;                                       \
                CP16(smaddr(psm + base + (st) * NHEADS * PAP + hh * PAP + j4),     \
                     src + ((size_t)(b * NHEADS + hh)) * TT + (j0) + j4);          \
            }                                                                      \
        } while (0)

    float acc[2][4];
    #pragma unroll
    for (int n = 0; n < 2; n++)
        #pragma unroll
        for (int r = 0; r < 4; r++) acc[n][r] = 0.f;

    PFILL(0, 0);  CP_COMMIT();
    PFILL(1, 32); CP_COMMIT();

    for (int s = 0; s < 64; s++) {
        CP_WAIT1();          // {s, s+1} pending here: wait1 guarantees stage s landed
        __syncthreads();
        if (s + 2 < 64) PFILL((s + 2) % 3, (s + 2) * 32);
        CP_COMMIT();

        int buf = s % 3;
        const float*    hs = psm + buf * 32 * PBP;
        const unsigned* ah = (const unsigned*)(psm + AH0 + buf * NHEADS * PAP);
        const unsigned* al = (const unsigned*)(psm + AL0 + buf * NHEADS * PAP);

        #pragma unroll
        for (int ks = 0; ks < 4; ks++) {
            int k0 = ks * 8;
            unsigned a0h = ah[(grp)     * PAP + k0 + thr];
            unsigned a1h = ah[(grp + 8) * PAP + k0 + thr];
            unsigned a2h = ah[(grp)     * PAP + k0 + thr + 4];
            unsigned a3h = ah[(grp + 8) * PAP + k0 + thr + 4];
            unsigned a0l = al[(grp)     * PAP + k0 + thr];
            unsigned a1l = al[(grp + 8) * PAP + k0 + thr];
            unsigned a2l = al[(grp)     * PAP + k0 + thr + 4];
            unsigned a3l = al[(grp + 8) * PAP + k0 + thr + 4];
            #pragma unroll
            for (int n = 0; n < 2; n++) {
                int ib = wid * 16 + n * 8 + grp;
                float f0 = hs[(k0 + thr)     * PBP + ib];
                float f1 = hs[(k0 + thr + 4) * PBP + ib];
                unsigned b0h = cvt_tf32(f0);
                unsigned b1h = cvt_tf32(f1);
                unsigned b0l = cvt_tf32(f0 - __uint_as_float(b0h));
                unsigned b1l = cvt_tf32(f1 - __uint_as_float(b1h));
                MMA8(acc[n][0], acc[n][1], acc[n][2], acc[n][3],
                     a0h, a1h, a2h, a3h, b0h, b1h);
                MMA8(acc[n][0], acc[n][1], acc[n][2], acc[n][3],
                     a0h, a1h, a2h, a3h, b0l, b1l);
                MMA8(acc[n][0], acc[n][1], acc[n][2], acc[n][3],
                     a0l, a1l, a2l, a3l, b0h, b1h);
            }
        }
    }

    #pragma unroll
    for (int n = 0; n < 2; n++) {
        int i = i0 + wid * 16 + n * 8 + 2 * thr;
        *(float2*)(g_pooled + ((size_t)(b * NHEADS + grp))     * HID + i) =
            make_float2(acc[n][0], acc[n][1]);
        *(float2*)(g_pooled + ((size_t)(b * NHEADS + grp + 8)) * HID + i) =
            make_float2(acc[n][2], acc[n][3]);
    }
}

// ---------------- kernel 5: per-head V projection with weight-tile reuse ----------------
__global__ void __launch_bounds__(256) k_vproj(const float* __restrict__ kvw,
                                               const float* __restrict__ kvb) {
    int h  = blockIdx.x;
    int dg = blockIdx.y;
    __shared__ float p_s[32][64];
    __shared__ float w_s[64 * 32];
    int tid = threadIdx.x;
    int d   = tid & 31;
    int bg  = tid >> 5;

    float acc[4] = {0.f, 0.f, 0.f, 0.f};

    for (int c = 0; c < 16; c++) {
        int i0 = c * 64;
        __syncthreads();
        #pragma unroll
        for (int p = 0; p < 2; p++) {
            int o4 = (p * 256 + tid) * 4;
            int i  = o4 >> 5;
            int cc = o4 & 31;
            *(float4*)&w_s[o4] =
                *(const float4*)(kvw + (size_t)(i0 + i) * (2 * HID) + HID + h * 64 + dg * 32 + cc);
        }
        #pragma unroll
        for (int p = 0; p < 2; p++) {
            int idx = p * 256 + tid;
            int b   = idx >> 4;
            int c4  = (idx & 15) * 4;
            *(float4*)&p_s[b][c4] =
                *(const float4*)(g_pooled + ((size_t)b * NHEADS + h) * HID + i0 + c4);
        }
        __syncthreads();

        #pragma unroll 8
        for (int i = 0; i < 64; i++) {
            float w = w_s[i * 32 + d];
            #pragma unroll
            for (int bb = 0; bb < 4; bb++)
                acc[bb] += p_s[bg * 4 + bb][i] * w;
        }
    }

    float bias = kvb[HID + h * 64 + dg * 32 + d];
    #pragma unroll
    for (int bb = 0; bb < 4; bb++) {
        int b = bg * 4 + bb;
        g_outv[b * HID + h * 64 + dg * 32 + d] = acc[bb] + bias;
    }
}

// ---------------- kernel 6: final GEMM [32,1024] x [1024,1024], c-sliced ----------------
__global__ void __launch_bounds__(256) k_final(const float* __restrict__ outw) {
    int p0 = blockIdx.x * 128;
    int c0 = blockIdx.y * 64;
    __shared__ float outv_s[32][64];
    int tid = threadIdx.x;
    for (int t = tid; t < 32 * 64; t += 256) {
        int bb2 = t >> 6;
        int cc  = t & 63;
        outv_s[bb2][cc] = g_outv[bb2 * HID + c0 + cc];
    }
    __syncthreads();

    int p   = tid & 127;
    int bh2 = tid >> 7;
    float acc[16];
    #pragma unroll
    for (int n = 0; n < 16; n++) acc[n] = 0.f;

    #pragma unroll 4
    for (int cc = 0; cc < 64; cc++) {
        float w = __ldg(outw + (size_t)(c0 + cc) * 1024 + p0 + p);
        #pragma unroll
        for (int n = 0; n < 16; n++) acc[n] += outv_s[bh2 * 16 + n][cc] * w;
    }
    #pragma unroll
    for (int n = 0; n < 16; n++)
        g_fpart[((size_t)blockIdx.y * BB + bh2 * 16 + n) * 1024 + p0 + p] = acc[n];
}

__global__ void k_finred(const float* __restrict__ outb, float* __restrict__ out) {
    int idx = blockIdx.x * 256 + threadIdx.x;
    int b = idx >> 10;
    int p = idx & 1023;
    float s = outb[p];
    #pragma unroll
    for (int cs = 0; cs < 16; cs++) s += g_fpart[((size_t)cs * BB + b) * 1024 + p];
    out[idx] = s;
}

// ---------------- launch ----------------
extern "C" void kernel_launch(void* const* d_in, const int* in_sizes, int n_in,
                              void* d_out, int out_size) {
    const float* hid  = (const float*)d_in[0];
    const int*   mask = (const int*)  d_in[1];
    const float* kvw  = (const float*)d_in[2];
    const float* kvb  = (const float*)d_in[3];
    const float* outw = (const float*)d_in[4];
    const float* outb = (const float*)d_in[5];
    const float* q    = (const float*)d_in[6];
    float* out = (float*)d_out;

    cudaFuncSetAttribute(k_logits, cudaFuncAttributeMaxDynamicSharedMemorySize, 61440);
    cudaFuncSetAttribute(k_pool,   cudaFuncAttributeMaxDynamicSharedMemorySize, 66048);

    k_wq     <<<2048, 256>>>(q, kvw, kvb);
    k_logits <<<256, 256, 61440>>>(hid);
    k_softmax<<<512, 256>>>(mask);
    k_pool   <<<dim3(8, 32), 256, 66048>>>(hid);
    k_vproj  <<<dim3(16, 2), 256>>>(kvw, kvb);
    k_final  <<<dim3(8, 16), 256>>>(outw);
    k_finred <<<128, 256>>>(outb, out);
}

// round 14
// speedup vs baseline: 1.4982x; 1.1032x over previous
#include <cuda_runtime.h>
#include <cstdint>

#define NHEADS 16
#define HID    1024
#define TT     2048
#define BB     32

typedef unsigned long long ull;

// ---------------- device scratch (no allocations allowed) ----------------
__device__ float g_wqh[NHEADS * HID];                 // tf32-hi of folded q @ kv_w
__device__ float g_wql[NHEADS * HID];                 // tf32-lo residual
__device__ float g_c[NHEADS];
__device__ float g_logits[BB * NHEADS * TT];          // logits -> attn tf32-hi (in place)
__device__ float g_attnl[BB * NHEADS * TT];           // attn tf32-lo residual
__device__ float g_pooled[BB * NHEADS * HID];         // pooled hidden
__device__ float g_outv[BB * HID];
__device__ float g_fpart[16 * BB * HID];

static __device__ __forceinline__ unsigned smaddr(const void* p) {
    return (unsigned)__cvta_generic_to_shared(p);
}
#define CP16(dst, src)  asm volatile("cp.async.cg.shared.global [%0], [%1], 16;" :: "r"(dst), "l"(src))
#define CP_COMMIT()     asm volatile("cp.async.commit_group;" ::: "memory")
#define CP_WAIT1()      asm volatile("cp.async.wait_group 1;" ::: "memory")
#define CP_WAIT2()      asm volatile("cp.async.wait_group 2;" ::: "memory")

static __device__ __forceinline__ unsigned cvt_tf32(float x) {
    unsigned r;
    asm("cvt.rna.tf32.f32 %0, %1;" : "=r"(r) : "f"(x));
    return r;
}
#define MMA8(d0, d1, d2, d3, a0, a1, a2, a3, b0, b1)                     \
    asm("mma.sync.aligned.m16n8k8.row.col.f32.tf32.tf32.f32 "            \
        "{%0,%1,%2,%3},{%4,%5,%6,%7},{%8,%9},{%0,%1,%2,%3};"             \
        : "+f"(d0), "+f"(d1), "+f"(d2), "+f"(d3)                         \
        : "r"(a0), "r"(a1), "r"(a2), "r"(a3), "r"(b0), "r"(b1))

// ---------------- kernel 1: fold query into kv_w (k half), emit tf32 hi/lo ----------------
__global__ void k_wq(const float* __restrict__ q,
                     const float* __restrict__ kvw,
                     const float* __restrict__ kvb) {
    int w = blockIdx.x * (blockDim.x >> 5) + (threadIdx.x >> 5);
    int lane = threadIdx.x & 31;
    if (w < NHEADS * HID) {
        int h = w & (NHEADS - 1);
        int i = w >> 4;
        const float* wr = kvw + (size_t)i * (2 * HID) + h * 64;
        const float* qr = q + h * 64;
        float s = qr[lane] * wr[lane] + qr[lane + 32] * wr[lane + 32];
        #pragma unroll
        for (int o = 16; o; o >>= 1) s += __shfl_xor_sync(0xffffffffu, s, o);
        if (lane == 0) {
            float v = 0.125f * s;
            unsigned hi = cvt_tf32(v);
            g_wqh[h * HID + i] = __uint_as_float(hi);
            g_wql[h * HID + i] = __uint_as_float(cvt_tf32(v - __uint_as_float(hi)));
        }
    }
    if (blockIdx.x == 0 && threadIdx.x < NHEADS) {
        int h = threadIdx.x;
        float s = 0.f;
        for (int d = 0; d < 64; d++) s += q[h * 64 + d] * kvb[h * 64 + d];
        g_c[h] = 0.125f * s;
    }
}

// ---------------- kernel 2: logits via tensor cores (measured-best R11) ----------------
#define LCH 16
#define HP  20
__global__ void __launch_bounds__(256) k_logits(const float* __restrict__ hid) {
    extern __shared__ __align__(16) float hsm[];        // [3][256][20]
    __shared__ __align__(16) float wq_s[3][2][NHEADS][HP];
    int tid = threadIdx.x;
    int wid = tid >> 5, l = tid & 31;
    int grp = l >> 2,   thr = l & 3;
    const float* hblk = hid + (size_t)blockIdx.x * 256 * HID;

    float acc[2][2][4];
    #pragma unroll
    for (int m = 0; m < 2; m++)
        #pragma unroll
        for (int n = 0; n < 2; n++)
            #pragma unroll
            for (int r = 0; r < 4; r++) acc[m][n][r] = 0.f;

    #define LFILL(st, kc)                                                          \
        do {                                                                       \
            _Pragma("unroll")                                                      \
            for (int p = 0; p < 4; p++) {                                          \
                int idx = p * 256 + tid;                                           \
                int row = idx >> 2;                                                \
                int q4  = (idx & 3) * 4;                                           \
                CP16(smaddr(hsm + ((st) * 256 + row) * HP + q4),                   \
                     hblk + (size_t)row * HID + (kc) + q4);                        \
            }                                                                      \
            if (tid < 128) {                                                       \
                int half = tid >> 6;                                               \
                int hh   = (tid >> 2) & 15;                                        \
                int kq   = (tid & 3) * 4;                                          \
                const float* src = half ? g_wql : g_wqh;                           \
                CP16(smaddr(&wq_s[st][half][hh][kq]), src + hh * HID + (kc) + kq); \
            }                                                                      \
        } while (0)

    LFILL(0, 0);   CP_COMMIT();
    LFILL(1, LCH); CP_COMMIT();

    for (int c = 0; c < HID / LCH; c++) {
        if (c + 2 < HID / LCH) {
            int st = (c + 2) % 3;
            int kc = (c + 2) * LCH;
            LFILL(st, kc);
        }
        CP_COMMIT();
        CP_WAIT2();
        __syncthreads();

        int buf = c % 3;
        const float*    hs = hsm + buf * 256 * HP;
        const unsigned* wh = (const unsigned*)&wq_s[buf][0][0][0];
        const unsigned* wl = (const unsigned*)&wq_s[buf][1][0][0];

        #pragma unroll
        for (int s = 0; s < 2; s++) {
            int k0 = s * 8;
            unsigned b0h0 = wh[(grp)     * HP + k0 + thr];
            unsigned b1h0 = wh[(grp)     * HP + k0 + thr + 4];
            unsigned b0h1 = wh[(8 + grp) * HP + k0 + thr];
            unsigned b1h1 = wh[(8 + grp) * HP + k0 + thr + 4];
            unsigned b0l0 = wl[(grp)     * HP + k0 + thr];
            unsigned b1l0 = wl[(grp)     * HP + k0 + thr + 4];
            unsigned b0l1 = wl[(8 + grp) * HP + k0 + thr];
            unsigned b1l1 = wl[(8 + grp) * HP + k0 + thr + 4];
            #pragma unroll
            for (int m = 0; m < 2; m++) {
                int jb = wid * 32 + m * 16;
                unsigned a0 = cvt_tf32(hs[(jb + grp)     * HP + k0 + thr]);
                unsigned a1 = cvt_tf32(hs[(jb + grp + 8) * HP + k0 + thr]);
                unsigned a2 = cvt_tf32(hs[(jb + grp)     * HP + k0 + thr + 4]);
                unsigned a3 = cvt_tf32(hs[(jb + grp + 8) * HP + k0 + thr + 4]);
                MMA8(acc[m][0][0], acc[m][0][1], acc[m][0][2], acc[m][0][3],
                     a0, a1, a2, a3, b0h0, b1h0);
                MMA8(acc[m][0][0], acc[m][0][1], acc[m][0][2], acc[m][0][3],
                     a0, a1, a2, a3, b0l0, b1l0);
                MMA8(acc[m][1][0], acc[m][1][1], acc[m][1][2], acc[m][1][3],
                     a0, a1, a2, a3, b0h1, b1h1);
                MMA8(acc[m][1][0], acc[m][1][1], acc[m][1][2], acc[m][1][3],
                     a0, a1, a2, a3, b0l1, b1l1);
            }
        }
        __syncthreads();
    }

    int jg = blockIdx.x * 256 + wid * 32;
    int b  = jg >> 11;
    #pragma unroll
    for (int m = 0; m < 2; m++) {
        int j0 = (jg + m * 16 + grp) & 2047;
        #pragma unroll
        for (int n = 0; n < 2; n++) {
            int h0 = n * 8 + 2 * thr;
            g_logits[((size_t)(b * NHEADS + h0))     * TT + j0]     = acc[m][n][0] + g_c[h0];
            g_logits[((size_t)(b * NHEADS + h0 + 1)) * TT + j0]     = acc[m][n][1] + g_c[h0 + 1];
            g_logits[((size_t)(b * NHEADS + h0))     * TT + j0 + 8] = acc[m][n][2] + g_c[h0];
            g_logits[((size_t)(b * NHEADS + h0 + 1)) * TT + j0 + 8] = acc[m][n][3] + g_c[h0 + 1];
        }
    }
}

// ---------------- kernel 3: softmax -> attn tf32 hi (in place) + lo ----------------
__global__ void __launch_bounds__(256) k_softmax(const int* __restrict__ mask) {
    int bh = blockIdx.x;
    int b  = bh >> 4;
    float* row = g_logits + (size_t)bh * TT;
    float* rowl = g_attnl + (size_t)bh * TT;
    const int* mrow = mask + (size_t)b * TT;
    int tid = threadIdx.x;

    float x[8];
    float mx = -1e30f;
    #pragma unroll
    for (int r = 0; r < 8; r++) {
        int j = tid + r * 256;
        float v = row[j];
        if (mrow[j] == 0) v = -1e30f;
        x[r] = v;
        mx = fmaxf(mx, v);
    }
    __shared__ float red[8];
    #pragma unroll
    for (int o = 16; o; o >>= 1) mx = fmaxf(mx, __shfl_xor_sync(0xffffffffu, mx, o));
    if ((tid & 31) == 0) red[tid >> 5] = mx;
    __syncthreads();
    mx = red[0];
    #pragma unroll
    for (int w = 1; w < 8; w++) mx = fmaxf(mx, red[w]);

    float sum = 0.f;
    #pragma unroll
    for (int r = 0; r < 8; r++) { float e = __expf(x[r] - mx); x[r] = e; sum += e; }
    #pragma unroll
    for (int o = 16; o; o >>= 1) sum += __shfl_xor_sync(0xffffffffu, sum, o);
    __syncthreads();
    if ((tid & 31) == 0) red[tid >> 5] = sum;
    __syncthreads();
    sum = red[0] + red[1] + red[2] + red[3] + red[4] + red[5] + red[6] + red[7];
    float inv = __fdividef(1.f, sum);
    #pragma unroll
    for (int r = 0; r < 8; r++) {
        int j = tid + r * 256;
        float w = x[r] * inv;
        unsigned hi = cvt_tf32(w);
        row[j]  = __uint_as_float(hi);
        rowl[j] = __uint_as_float(cvt_tf32(w - __uint_as_float(hi)));
    }
}

// ---------------- kernel 4: pool via tensor cores ----------------
// CTA = (i-chunk 128, b): C[16h,128i] = attn[16h,2048j] @ hid[2048j,128i].
// D += ah*bh + al*bh (hid tf32-hi only; rounding cancels over 2048-j sums).
// 64 stages of 32 j, 3-stage ring, wait-first + CP_WAIT1.
#define PBP 136
#define PAP 36
#define HID3 (3 * 32 * PBP)                 // 13056 floats
#define AH0  HID3                           // attn-hi stages
#define AL0  (HID3 + 3 * NHEADS * PAP)      // attn-lo stages
__global__ void __launch_bounds__(256) k_pool(const float* __restrict__ hid) {
    extern __shared__ __align__(16) float psm[];
    int b   = blockIdx.y;
    int i0  = blockIdx.x * 128;
    int tid = threadIdx.x;
    int wid = tid >> 5, l = tid & 31;
    int grp = l >> 2,   thr = l & 3;

    const float* hbase = hid + (size_t)b * TT * HID + i0;

    #define PFILL(st, j0)                                                          \
        do {                                                                       \
            _Pragma("unroll")                                                      \
            for (int p = 0; p < 4; p++) {                                          \
                int idx = p * 256 + tid;                                           \
                int row = idx >> 5;                                                \
                int c4  = (idx & 31) * 4;                                          \
                CP16(smaddr(psm + (st) * 32 * PBP + row * PBP + c4),               \
                     hbase + (size_t)((j0) + row) * HID + c4);                     \
            }                                                                      \
            {                                                                      \
                int half = tid >> 7;                                               \
                int hh   = (tid >> 3) & 15;                                        \
                int j4   = (tid & 7) * 4;                                          \
                const float* src = half ? g_attnl : g_logits;                      \
                int base = half ? AL0 : AH0;                                       \
                CP16(smaddr(psm + base + (st) * NHEADS * PAP + hh * PAP + j4),     \
                     src + ((size_t)(b * NHEADS + hh)) * TT + (j0) + j4);          \
            }                                                                      \
        } while (0)

    float acc[2][4];
    #pragma unroll
    for (int n = 0; n < 2; n++)
        #pragma unroll
        for (int r = 0; r < 4; r++) acc[n][r] = 0.f;

    PFILL(0, 0);  CP_COMMIT();
    PFILL(1, 32); CP_COMMIT();

    for (int s = 0; s < 64; s++) {
        CP_WAIT1();          // {s, s+1} pending here: wait1 guarantees stage s landed
        __syncthreads();
        if (s + 2 < 64) PFILL((s + 2) % 3, (s + 2) * 32);
        CP_COMMIT();

        int buf = s % 3;
        const float*    hs = psm + buf * 32 * PBP;
        const unsigned* ah = (const unsigned*)(psm + AH0 + buf * NHEADS * PAP);
        const unsigned* al = (const unsigned*)(psm + AL0 + buf * NHEADS * PAP);

        #pragma unroll
        for (int ks = 0; ks < 4; ks++) {
            int k0 = ks * 8;
            unsigned a0h = ah[(grp)     * PAP + k0 + thr];
            unsigned a1h = ah[(grp + 8) * PAP + k0 + thr];
            unsigned a2h = ah[(grp)     * PAP + k0 + thr + 4];
            unsigned a3h = ah[(grp + 8) * PAP + k0 + thr + 4];
            unsigned a0l = al[(grp)     * PAP + k0 + thr];
            unsigned a1l = al[(grp + 8) * PAP + k0 + thr];
            unsigned a2l = al[(grp)     * PAP + k0 + thr + 4];
            unsigned a3l = al[(grp + 8) * PAP + k0 + thr + 4];
            #pragma unroll
            for (int n = 0; n < 2; n++) {
                int ib = wid * 16 + n * 8 + grp;
                unsigned b0h = cvt_tf32(hs[(k0 + thr)     * PBP + ib]);
                unsigned b1h = cvt_tf32(hs[(k0 + thr + 4) * PBP + ib]);
                MMA8(acc[n][0], acc[n][1], acc[n][2], acc[n][3],
                     a0h, a1h, a2h, a3h, b0h, b1h);
                MMA8(acc[n][0], acc[n][1], acc[n][2], acc[n][3],
                     a0l, a1l, a2l, a3l, b0h, b1h);
            }
        }
    }

    #pragma unroll
    for (int n = 0; n < 2; n++) {
        int i = i0 + wid * 16 + n * 8 + 2 * thr;
        *(float2*)(g_pooled + ((size_t)(b * NHEADS + grp))     * HID + i) =
            make_float2(acc[n][0], acc[n][1]);
        *(float2*)(g_pooled + ((size_t)(b * NHEADS + grp + 8)) * HID + i) =
            make_float2(acc[n][2], acc[n][3]);
    }
}

// ---------------- kernel 5: per-head V projection with weight-tile reuse ----------------
__global__ void __launch_bounds__(256) k_vproj(const float* __restrict__ kvw,
                                               const float* __restrict__ kvb) {
    int h  = blockIdx.x;
    int dg = blockIdx.y;
    __shared__ float p_s[32][64];
    __shared__ float w_s[64 * 32];
    int tid = threadIdx.x;
    int d   = tid & 31;
    int bg  = tid >> 5;

    float acc[4] = {0.f, 0.f, 0.f, 0.f};

    for (int c = 0; c < 16; c++) {
        int i0 = c * 64;
        __syncthreads();
        #pragma unroll
        for (int p = 0; p < 2; p++) {
            int o4 = (p * 256 + tid) * 4;
            int i  = o4 >> 5;
            int cc = o4 & 31;
            *(float4*)&w_s[o4] =
                *(const float4*)(kvw + (size_t)(i0 + i) * (2 * HID) + HID + h * 64 + dg * 32 + cc);
        }
        #pragma unroll
        for (int p = 0; p < 2; p++) {
            int idx = p * 256 + tid;
            int b   = idx >> 4;
            int c4  = (idx & 15) * 4;
            *(float4*)&p_s[b][c4] =
                *(const float4*)(g_pooled + ((size_t)b * NHEADS + h) * HID + i0 + c4);
        }
        __syncthreads();

        #pragma unroll 8
        for (int i = 0; i < 64; i++) {
            float w = w_s[i * 32 + d];
            #pragma unroll
            for (int bb = 0; bb < 4; bb++)
                acc[bb] += p_s[bg * 4 + bb][i] * w;
        }
    }

    float bias = kvb[HID + h * 64 + dg * 32 + d];
    #pragma unroll
    for (int bb = 0; bb < 4; bb++) {
        int b = bg * 4 + bb;
        g_outv[b * HID + h * 64 + dg * 32 + d] = acc[bb] + bias;
    }
}

// ---------------- kernel 6: final GEMM [32,1024] x [1024,1024], c-sliced ----------------
__global__ void __launch_bounds__(256) k_final(const float* __restrict__ outw) {
    int p0 = blockIdx.x * 128;
    int c0 = blockIdx.y * 64;
    __shared__ float outv_s[32][64];
    int tid = threadIdx.x;
    for (int t = tid; t < 32 * 64; t += 256) {
        int bb2 = t >> 6;
        int cc  = t & 63;
        outv_s[bb2][cc] = g_outv[bb2 * HID + c0 + cc];
    }
    __syncthreads();

    int p   = tid & 127;
    int bh2 = tid >> 7;
    float acc[16];
    #pragma unroll
    for (int n = 0; n < 16; n++) acc[n] = 0.f;

    #pragma unroll 4
    for (int cc = 0; cc < 64; cc++) {
        float w = __ldg(outw + (size_t)(c0 + cc) * 1024 + p0 + p);
        #pragma unroll
        for (int n = 0; n < 16; n++) acc[n] += outv_s[bh2 * 16 + n][cc] * w;
    }
    #pragma unroll
    for (int n = 0; n < 16; n++)
        g_fpart[((size_t)blockIdx.y * BB + bh2 * 16 + n) * 1024 + p0 + p] = acc[n];
}

__global__ void k_finred(const float* __restrict__ outb, float* __restrict__ out) {
    int idx = blockIdx.x * 256 + threadIdx.x;
    int b = idx >> 10;
    int p = idx & 1023;
    float s = outb[p];
    #pragma unroll
    for (int cs = 0; cs < 16; cs++) s += g_fpart[((size_t)cs * BB + b) * 1024 + p];
    out[idx] = s;
}

// ---------------- launch ----------------
extern "C" void kernel_launch(void* const* d_in, const int* in_sizes, int n_in,
                              void* d_out, int out_size) {
    const float* hid  = (const float*)d_in[0];
    const int*   mask = (const int*)  d_in[1];
    const float* kvw  = (const float*)d_in[2];
    const float* kvb  = (const float*)d_in[3];
    const float* outw = (const float*)d_in[4];
    const float* outb = (const float*)d_in[5];
    const float* q    = (const float*)d_in[6];
    float* out = (float*)d_out;

    cudaFuncSetAttribute(k_logits, cudaFuncAttributeMaxDynamicSharedMemorySize, 61440);
    cudaFuncSetAttribute(k_pool,   cudaFuncAttributeMaxDynamicSharedMemorySize, 66048);

    k_wq     <<<2048, 256>>>(q, kvw, kvb);
    k_logits <<<256, 256, 61440>>>(hid);
    k_softmax<<<512, 256>>>(mask);
    k_pool   <<<dim3(8, 32), 256, 66048>>>(hid);
    k_vproj  <<<dim3(16, 2), 256>>>(kvw, kvb);
    k_final  <<<dim3(8, 16), 256>>>(outw);
    k_finred <<<128, 256>>>(outb, out);
}